// round 15
// baseline (speedup 1.0000x reference)
#include <cuda_runtime.h>
#include <cuda_bf16.h>

// Problem constants
#define B_  16
#define R_  64
#define S_  128
#define M_  64
#define L_  128
#define E_  4032            // R*R - R

// Output layout (float elements), 5 concatenated outputs:
#define OFF_INC_ADD  0ull
#define OFF_INC_GAIN 131072ull
#define OFF_MEAN     262144ull
#define OFF_LOG      4456448ull
#define OFF_MSG      8650752ull

// Shared layout (floats), total 24832 floats = 99328 B dynamic smem
#define XS_OFF    0            // xs[b][s] stride 132: 16*132 = 2112
#define PA_OFF    2112         // SubA weights: w2 64*132=8448 / w3 128*68=8704
#define QB_OFF    10816        // SubB weights
#define SMEAN_OFF 19520        // smean[b][m] stride 68: 1088 -> ends 20608
#define SADD_OFF  20608        // sadd[b][l]  stride 132: 2112 -> ends 22720
#define SGAIN_OFF 22720        // sgain[b][l] stride 132: 2112 -> ends 24832
#define SMEM_FLOATS 24832
#define XSS 132                // xs row stride (batch-distinct banks: 4b)
#define W2S 132                // phase-2 weight row stride (128+4)
#define W3S 68                 // phase-3 weight row stride (64+4)
#define SMS 68                 // smean row stride
#define SAS 132                // sadd/sgain row stride

typedef unsigned long long ull;

// ---------------- packed f32x2 helpers ----------------
__device__ __forceinline__ ull fma2(ull a, ull b, ull c) {
    ull d;
    asm("fma.rn.f32x2 %0, %1, %2, %3;" : "=l"(d) : "l"(a), "l"(b), "l"(c));
    return d;
}
__device__ __forceinline__ void unpk(ull v, float& lo, float& hi) {
    asm("mov.b64 {%0, %1}, %2;" : "=f"(lo), "=f"(hi) : "l"(v));
}
__device__ __forceinline__ void red_add_v4(float* p, float4 v) {
    asm volatile("red.global.add.v4.f32 [%0], {%1, %2, %3, %4};"
                 :: "l"(p), "f"(v.x), "f"(v.y), "f"(v.z), "f"(v.w) : "memory");
}
__device__ __forceinline__ void cpa16(float* dst_smem, const float* src) {
    unsigned sa = (unsigned)__cvta_generic_to_shared(dst_smem);
    asm volatile("cp.async.cg.shared.global [%0], [%1], 16;" :: "r"(sa), "l"(src));
}
__device__ __forceinline__ void cp_commit() { asm volatile("cp.async.commit_group;"); }
__device__ __forceinline__ void cp_wait0()  { asm volatile("cp.async.wait_group 0;" ::: "memory"); }
__device__ __forceinline__ void bar_sync(int id, int cnt) {
    asm volatile("bar.sync %0, %1;" :: "r"(id), "r"(cnt) : "memory");
}
__device__ __forceinline__ void bar_arrive(int id, int cnt) {
    asm volatile("bar.arrive %0, %1;" :: "r"(id), "r"(cnt) : "memory");
}

// ---------------- init: zero inc regions + scat diagonals (vectorized) ----
__global__ void init_kernel(float* __restrict__ out) {
    int idx = blockIdx.x * blockDim.x + threadIdx.x;   // grid covers 65536
    if (idx < 65536)
        reinterpret_cast<float4*>(out)[idx] = make_float4(0.f, 0.f, 0.f, 0.f);
    if (idx < 49152) {
        int o    = idx >> 14;              // 0..2
        int rest = idx & 16383;
        int b    = rest >> 10;             // 0..15
        int r    = (rest >> 4) & 63;       // 0..63
        int q    = rest & 15;              // 0..15
        ull base = (o == 0) ? OFF_MEAN : ((o == 1) ? OFF_LOG : OFF_MSG);
        ull a = base + (((ull)(b * R_ + r) * R_ + r) * M_) + q * 4;
        *reinterpret_cast<float4*>(out + a) = make_float4(0.f, 0.f, 0.f, 0.f);
    }
}

// ---------------- main: one block per edge, two 128-thread sub-pipelines ----
__global__ __launch_bounds__(256, 2) void edge_kernel(
    const float* __restrict__ source,
    const float* __restrict__ mean_w,
    const float* __restrict__ mean_b,
    const float* __restrict__ logstd_w,
    const float* __restrict__ logstd_b,
    const float* __restrict__ add_w,
    const float* __restrict__ gain_w,
    float* __restrict__ out)
{
    extern __shared__ float sm[];
    float* xs    = sm + XS_OFF;      // [b][s] stride 132 (4-addr/phase reads)
    float* smean = sm + SMEAN_OFF;   // [b][m] stride 68
    float* sadd  = sm + SADD_OFF;    // [b][l] stride 132
    float* sgain = sm + SGAIN_OFF;

    const int e = blockIdx.x;
    const int s_idx = e / (R_ - 1);
    const int rem   = e % (R_ - 1);
    const int t_idx = rem + (rem >= s_idx ? 1 : 0);
    const int tid = threadIdx.x;
    const bool isA = (tid < 128);
    const int  u   = tid & 127;
    float* WB = sm + (isA ? PA_OFF : QB_OFF);

    // ---- staging 1: xs (all threads) + phase-2 weights (per sub) ----
    #pragma unroll
    for (int k = 0; k < 2; k++) {
        int i = tid + k * 256;
        int b = i >> 5, c = i & 31;
        cpa16(xs + b * XSS + c * 4,
              source + (ull)b * (R_ * S_) + (ull)s_idx * S_ + c * 4);
    }
    {
        const float* w2src = isA ? mean_w : logstd_w;
        #pragma unroll
        for (int k = 0; k < 16; k++) {
            int c   = u + k * 128;
            int row = c >> 5;
            int col = c & 31;
            cpa16(WB + row * W2S + col * 4,
                  w2src + ((ull)e * M_ + row) * S_ + col * 4);
        }
    }
    cp_commit();
    cp_wait0();
    __syncthreads();

    // ---- phase 2: quad-broadcast weights — rows (lq, lq+32), batches bq+4i
    {
        const int lq = u >> 2;              // 0..31 (quad-shared -> bcast weights)
        const int bq = u & 3;               // 0..3

        const float* w0 = WB + lq * W2S;
        const float* w1 = WB + (lq + 32) * W2S;
        const float* bsrc = isA ? mean_b : logstd_b;
        const float bias0 = bsrc[(ull)e * M_ + lq];
        const float bias1 = bsrc[(ull)e * M_ + lq + 32];

        ull acc[2][4];
        #pragma unroll
        for (int r = 0; r < 2; r++)
            #pragma unroll
            for (int i = 0; i < 4; i++) acc[r][i] = 0ull;

        #pragma unroll 4
        for (int c = 0; c < 16; c++) {      // 8 s per chunk
            const int s0 = c * 8;
            ulonglong2 wa0 = *reinterpret_cast<const ulonglong2*>(w0 + s0);
            ulonglong2 wb0 = *reinterpret_cast<const ulonglong2*>(w0 + s0 + 4);
            ulonglong2 wa1 = *reinterpret_cast<const ulonglong2*>(w1 + s0);
            ulonglong2 wb1 = *reinterpret_cast<const ulonglong2*>(w1 + s0 + 4);
            #pragma unroll
            for (int i = 0; i < 4; i++) {
                const int b = bq + 4 * i;
                const float* xr = xs + b * XSS + s0;   // 4 addrs/phase, cf banks
                ulonglong2 xa = *reinterpret_cast<const ulonglong2*>(xr);
                ulonglong2 xb = *reinterpret_cast<const ulonglong2*>(xr + 4);
                acc[0][i] = fma2(xa.x, wa0.x, acc[0][i]);
                acc[0][i] = fma2(xa.y, wa0.y, acc[0][i]);
                acc[0][i] = fma2(xb.x, wb0.x, acc[0][i]);
                acc[0][i] = fma2(xb.y, wb0.y, acc[0][i]);
                acc[1][i] = fma2(xa.x, wa1.x, acc[1][i]);
                acc[1][i] = fma2(xa.y, wa1.y, acc[1][i]);
                acc[1][i] = fma2(xb.x, wb1.x, acc[1][i]);
                acc[1][i] = fma2(xb.y, wb1.y, acc[1][i]);
            }
        }

        const ull cellb = (ull)(s_idx * R_ + t_idx) * M_;
        #pragma unroll
        for (int r = 0; r < 2; r++) {
            const int m = lq + 32 * r;
            const float bias = r ? bias1 : bias0;
            #pragma unroll
            for (int i = 0; i < 4; i++) {
                const int b = bq + 4 * i;
                float lo, hi;
                unpk(acc[r][i], lo, hi);
                float v = lo + hi + bias;
                ull a = (ull)b * (R_ * R_ * M_) + cellb + m;
                if (isA) {
                    smean[b * SMS + m] = v;
                    out[OFF_MEAN + a] = v;
                    out[OFF_MSG  + a] = v;          // msg == mean
                } else {
                    out[OFF_LOG + a] = v;
                }
            }
        }
    }

    // ---- sub barriers: free own weight buffer; publish smean (A -> B) ----
    if (isA) { bar_sync(1, 128); bar_arrive(3, 256); }
    else     { bar_sync(2, 128); }

    // ---- staging 2: phase-3 weights (per sub) ----
    {
        const float* w3src = isA ? add_w : gain_w;
        #pragma unroll
        for (int k = 0; k < 16; k++) {
            int c   = u + k * 128;
            int row = c >> 4;
            int col = c & 15;
            cpa16(WB + row * W3S + col * 4,
                  w3src + ((ull)e * L_ + row) * M_ + col * 4);
        }
    }
    cp_commit();
    cp_wait0();
    if (isA) { bar_sync(1, 128); }
    else     { bar_sync(2, 128); bar_sync(3, 256); }  // wait smean from SubA

    // ---- phase 3: 4 rows/thread (lp+32r), 4 batches/thread (bq3+4i) ----
    {
        const int lp  = u >> 2;             // 0..31 (quad-shared -> bcast weights)
        const int bq3 = u & 3;              // 0..3

        ull acc[4][4];
        #pragma unroll
        for (int r = 0; r < 4; r++)
            #pragma unroll
            for (int i = 0; i < 4; i++) acc[r][i] = 0ull;

        #pragma unroll 2
        for (int c = 0; c < 8; c++) {       // 8 m per chunk
            const int m0 = c * 8;
            ulonglong2 wa[4], wb[4];
            #pragma unroll
            for (int r = 0; r < 4; r++) {
                const float* wr = WB + (lp + 32 * r) * W3S + m0;
                wa[r] = *reinterpret_cast<const ulonglong2*>(wr);
                wb[r] = *reinterpret_cast<const ulonglong2*>(wr + 4);
            }
            #pragma unroll
            for (int i = 0; i < 4; i++) {
                const int b = bq3 + 4 * i;
                const float* mr = smean + b * SMS + m0;
                ulonglong2 xa = *reinterpret_cast<const ulonglong2*>(mr);
                ulonglong2 xb = *reinterpret_cast<const ulonglong2*>(mr + 4);
                #pragma unroll
                for (int r = 0; r < 4; r++) {
                    acc[r][i] = fma2(xa.x, wa[r].x, acc[r][i]);
                    acc[r][i] = fma2(xa.y, wa[r].y, acc[r][i]);
                    acc[r][i] = fma2(xb.x, wb[r].x, acc[r][i]);
                    acc[r][i] = fma2(xb.y, wb[r].y, acc[r][i]);
                }
            }
        }

        float* sres = isA ? sadd : sgain;
        #pragma unroll
        for (int r = 0; r < 4; r++) {
            const int l = lp + 32 * r;
            #pragma unroll
            for (int i = 0; i < 4; i++) {
                const int b = bq3 + 4 * i;
                float lo, hi;
                unpk(acc[r][i], lo, hi);
                sres[b * SAS + l] = lo + hi;
            }
        }
    }
    if (isA) bar_sync(1, 128);
    else     bar_sync(2, 128);

    // ---- phase 4: vectorized scatter-add (each sub reduces its own array) ----
    {
        float* sres = isA ? sadd : sgain;
        const ull offI = isA ? OFF_INC_ADD : OFF_INC_GAIN;
        #pragma unroll
        for (int k = 0; k < 4; k++) {
            int i = u + 128 * k;
            int b = i >> 5;
            int q = i & 31;
            float4 v = *reinterpret_cast<const float4*>(sres + b * SAS + q * 4);
            float* dst = out + offI + (ull)(b * R_ + t_idx) * L_ + q * 4;
            red_add_v4(dst, v);
        }
    }
}

extern "C" void kernel_launch(void* const* d_in, const int* in_sizes, int n_in,
                              void* d_out, int out_size) {
    const float* source   = (const float*)d_in[0];
    const float* mean_w   = (const float*)d_in[1];
    const float* mean_b   = (const float*)d_in[2];
    const float* logstd_w = (const float*)d_in[3];
    const float* logstd_b = (const float*)d_in[4];
    const float* add_w    = (const float*)d_in[5];
    const float* gain_w   = (const float*)d_in[6];
    float* out = (float*)d_out;

    cudaFuncSetAttribute(edge_kernel, cudaFuncAttributeMaxDynamicSharedMemorySize,
                         SMEM_FLOATS * 4);

    init_kernel<<<256, 256>>>(out);
    edge_kernel<<<E_, 256, SMEM_FLOATS * 4>>>(source, mean_w, mean_b,
                                              logstd_w, logstd_b,
                                              add_w, gain_w, out);
}